// round 2
// baseline (speedup 1.0000x reference)
#include <cuda_runtime.h>
#include <cstdint>

#define B_   2
#define P_   8192
#define NNB  24
#define C1_  32
#define C2_  32
#define K_   13
#define A_   12
#define DR_  (C2_*A_)   /* 384 */
#define CA_  (C1_*A_)   /* 384 */
#define BP_  (B_*P_)    /* 16384 */

// ---- scratch (device globals; no allocation allowed) ----
__device__ float WT_g[K_*CA_*DR_];   // [k][c*12+a][d*12+r]  (~7.7 MB)
__device__ float md_g[BP_*3];        // mean_dir
__device__ float kpo_g[C2_*K_*3];    // normalized k_pos_ori
__device__ float be_g[C2_*A_];       // bias_eff[d][r]

// ---------------------------------------------------------------------------
// Kernel 1: build WT[d,c,k,a,r] = W[d,c,j] * k_pos_w[d,j],
//           j = idx_map[tivr[r,k]*A + tir[r,a]]
// ---------------------------------------------------------------------------
__global__ void build_wt(const float* __restrict__ W,
                         const float* __restrict__ kpw,
                         const int*   __restrict__ idx_map,
                         const int*   __restrict__ tivr,
                         const int*   __restrict__ tir) {
    int idx = blockIdx.x * blockDim.x + threadIdx.x;
    const int total = K_*CA_*DR_;
    for (; idx < total; idx += gridDim.x * blockDim.x) {
        int dr = idx % DR_;
        int t  = idx / DR_;
        int ca = t % CA_;
        int k  = t / CA_;
        int d = dr / A_, r = dr % A_;
        int c = ca / A_, a = ca % A_;
        int Kp = tivr[r*K_ + k];
        int Ap = tir[r*A_ + a];
        int j  = idx_map[Kp*A_ + Ap];
        WT_g[idx] = W[(d*C1_ + c)*36 + j] * kpw[d*36 + j];
    }
}

// ---------------------------------------------------------------------------
// Kernel 2: mean_dir[b,p] = mean_n normalize(vertices[b,nbr[b,p,n]] - vertices[b,p])
// ---------------------------------------------------------------------------
__global__ void mean_dir_k(const int* __restrict__ nbr_idx,
                           const float* __restrict__ verts) {
    int bp = blockIdx.x * blockDim.x + threadIdx.x;
    if (bp >= BP_) return;
    int b = bp >> 13;
    int p = bp & (P_-1);
    const float* vb = verts + b * P_ * 3;
    float vx = vb[p*3+0], vy = vb[p*3+1], vz = vb[p*3+2];
    float sx = 0.f, sy = 0.f, sz = 0.f;
    const int* ni = nbr_idx + bp * NNB;
#pragma unroll 4
    for (int n = 0; n < NNB; n++) {
        int q = ni[n];
        float dx = vb[q*3+0] - vx;
        float dy = vb[q*3+1] - vy;
        float dz = vb[q*3+2] - vz;
        float nrm = sqrtf(dx*dx + dy*dy + dz*dz);
        float s = 1.0f / fmaxf(nrm, 1e-12f);
        sx += dx*s; sy += dy*s; sz += dz*s;
    }
    const float inv = 1.0f / (float)NNB;
    md_g[bp*3+0] = sx * inv;
    md_g[bp*3+1] = sy * inv;
    md_g[bp*3+2] = sz * inv;
}

// ---------------------------------------------------------------------------
// Kernel 3: k_pos_ori (normalized) + bias_eff
// ---------------------------------------------------------------------------
__global__ void prep_small(const float* __restrict__ kpw,
                           const float* __restrict__ vs,
                           const int*   __restrict__ idx_map,
                           const int*   __restrict__ tivr,
                           const float* __restrict__ bias,
                           const int*   __restrict__ lvl) {
    int t = threadIdx.x;
    if (t < C2_*K_) {
        int d = t / K_, k = t % K_;
        float s0 = 0.f, s1 = 0.f, s2 = 0.f;
        for (int a = 0; a < A_; a++) {
            float w = kpw[d*36 + idx_map[k*A_ + a]];
            s0 += w * vs[a*3+0];
            s1 += w * vs[a*3+1];
            s2 += w * vs[a*3+2];
        }
        float nrm = sqrtf(s0*s0 + s1*s1 + s2*s2);
        float inv = 1.0f / fmaxf(nrm, 1e-12f);
        kpo_g[t*3+0] = s0*inv;
        kpo_g[t*3+1] = s1*inv;
        kpo_g[t*3+2] = s2*inv;
    }
    if (t < C2_*A_) {
        int d = t / A_, r = t % A_;
        float s = 0.f;
        for (int k = 0; k < K_; k++)
            s += bias[d*5 + lvl[tivr[r*K_ + k]]];
        be_g[t] = s;
    }
}

// ---------------------------------------------------------------------------
// Kernel 4: main segmented GEMM.
//   out[bp, d*12+r] = relu( bias_eff[d,r] +
//        sum_k  relu(md[bp]·kpo[d,k]) * sum_{c,a} WT[k][(c,a)][(d,r)]*fm[b,c,k,p,a] )
// Tile: 64 rows (bp) x 96 cols (8 d x 12 r), 256 threads, 4x6 micro-tile.
// Double-buffered smem: ONE __syncthreads per (k,c) tile.
// ---------------------------------------------------------------------------
__global__ __launch_bounds__(256) void equi_gemm(const float* __restrict__ fm,
                                                 float* __restrict__ out) {
    __shared__ float Ast[2][A_][64];   // [buf][a][row]
    __shared__ float Bs [2][A_][96];   // [buf][a][col]
    __shared__ float md_s[64][3];
    __shared__ float kpo_s[8][K_][3];

    const int tid = threadIdx.x;
    const int p0  = blockIdx.x * 64;   // global bp tile start
    const int n0  = blockIdx.y * 96;   // dr tile start
    const int b   = p0 >> 13;
    const int pp  = p0 & (P_-1);
    const int d0  = n0 / A_;           // first of 8 d's

    if (tid < 192)
        ((float*)md_s)[tid] = md_g[p0*3 + tid];
    for (int t = tid; t < 8*K_*3; t += 256) {          // 312 elems, strided (BUGFIX)
        int dl_  = t / (K_*3);
        int rest = t % (K_*3);
        ((float*)kpo_s)[t] = kpo_g[(d0+dl_)*(K_*3) + rest];
    }

    const int g  = tid >> 4;          // row group 0..15 -> rows g*4..g*4+3
    const int h  = tid & 15;          // col group 0..15 -> cols h*6..h*6+5
    const int dl = h >> 1;            // local d (0..7)
    const int r0 = (h & 1) * 6;       // r offset (0 or 6)

    float acc_o[4][6], acc_k[4][6];
#pragma unroll
    for (int i = 0; i < 4; i++)
#pragma unroll
        for (int j = 0; j < 6; j++) { acc_o[i][j] = 0.f; acc_k[i][j] = 0.f; }

    __syncthreads();

    float mdr[4][3];
#pragma unroll
    for (int i = 0; i < 4; i++) {
        mdr[i][0] = md_s[g*4+i][0];
        mdr[i][1] = md_s[g*4+i][1];
        mdr[i][2] = md_s[g*4+i][2];
    }

    float4 pa  = make_float4(0,0,0,0);
    float4 pb0 = make_float4(0,0,0,0);
    float4 pb1 = make_float4(0,0,0,0);

    const int rowB = tid / 24, c4B = tid - (tid/24)*24;     // pb0 slot
    const int qB   = tid + 256;
    const int rowB2 = qB / 24, c4B2 = qB - (qB/24)*24;      // pb1 slot (tid<32)

    auto loadAB = [&](int k, int c) {
        if (tid < 192) {
            const float4* fA = (const float4*)(fm +
                ((size_t)((b*C1_ + c)*K_ + k) * P_ + pp) * A_);
            pa = fA[tid];
        }
        const float* wb = WT_g + (size_t)(k*CA_ + c*A_) * DR_ + n0;
        pb0 = *(const float4*)(wb + rowB*DR_ + c4B*4);
        if (tid < 32)
            pb1 = *(const float4*)(wb + rowB2*DR_ + c4B2*4);
    };

    auto storeAB = [&](int s) {
        if (tid < 192) {
            int row = tid / 3;
            int a0  = (tid % 3) * 4;
            Ast[s][a0+0][row] = pa.x;
            Ast[s][a0+1][row] = pa.y;
            Ast[s][a0+2][row] = pa.z;
            Ast[s][a0+3][row] = pa.w;
        }
        *(float4*)&Bs[s][rowB][c4B*4] = pb0;
        if (tid < 32)
            *(float4*)&Bs[s][rowB2][c4B2*4] = pb1;
    };

    loadAB(0, 0);
    storeAB(0);
    __syncthreads();

    int k = 0, c = 0, buf = 0;
    for (int t = 0; t < K_*C1_; t++) {
        // prefetch next (k,c) into registers
        int c2 = c + 1, k2 = k;
        if (c2 == C1_) { c2 = 0; k2++; }
        if (k2 < K_) loadAB(k2, c2);

        // compute on current buffer
#pragma unroll
        for (int a = 0; a < A_; a++) {
            float4 av  = *(const float4*)&Ast[buf][a][g*4];
            float2 bv0 = *(const float2*)&Bs[buf][a][h*6+0];
            float2 bv1 = *(const float2*)&Bs[buf][a][h*6+2];
            float2 bv2 = *(const float2*)&Bs[buf][a][h*6+4];
            float aa[4] = {av.x, av.y, av.z, av.w};
            float bb[6] = {bv0.x, bv0.y, bv1.x, bv1.y, bv2.x, bv2.y};
#pragma unroll
            for (int i = 0; i < 4; i++)
#pragma unroll
                for (int j = 0; j < 6; j++)
                    acc_k[i][j] = fmaf(aa[i], bb[j], acc_k[i][j]);
        }

        // end of a k-segment: fold per-k pw weight
        if (c == C1_-1) {
            float kx = kpo_s[dl][k][0];
            float ky = kpo_s[dl][k][1];
            float kz = kpo_s[dl][k][2];
#pragma unroll
            for (int i = 0; i < 4; i++) {
                float w = fmaxf(mdr[i][0]*kx + mdr[i][1]*ky + mdr[i][2]*kz, 0.f);
#pragma unroll
                for (int j = 0; j < 6; j++) {
                    acc_o[i][j] = fmaf(w, acc_k[i][j], acc_o[i][j]);
                    acc_k[i][j] = 0.f;
                }
            }
        }

        // stage next tile into the other buffer; readers of that buffer
        // finished before the previous sync.
        if (k2 < K_) storeAB(buf ^ 1);
        __syncthreads();
        buf ^= 1; k = k2; c = c2;
    }

    // epilogue: bias + relu, write out[b, d, p, r]
    const int d = d0 + dl;
    float bev[6];
#pragma unroll
    for (int j = 0; j < 6; j++) bev[j] = be_g[d*A_ + r0 + j];
#pragma unroll
    for (int i = 0; i < 4; i++) {
        int bp = p0 + g*4 + i;
        int pl = bp & (P_-1);
        float* o = out + ((size_t)(b*C2_ + d) * P_ + pl) * A_ + r0;
#pragma unroll
        for (int j = 0; j < 6; j++)
            o[j] = fmaxf(acc_o[i][j] + bev[j], 0.f);
    }
}

// ---------------------------------------------------------------------------
extern "C" void kernel_launch(void* const* d_in, const int* in_sizes, int n_in,
                              void* d_out, int out_size) {
    const int*   nbr     = (const int*)  d_in[0];   // neighbor_index
    const float* verts   = (const float*)d_in[1];   // vertices
    const float* fm      = (const float*)d_in[2];   // feature_map
    const float* W       = (const float*)d_in[3];   // W
    const float* bias    = (const float*)d_in[4];   // bias
    const float* kpw     = (const float*)d_in[5];   // k_pos_w
    const float* vs      = (const float*)d_in[6];   // vs
    const int*   idx_map = (const int*)  d_in[7];   // idx_map
    const int*   tivr    = (const int*)  d_in[8];   // trace_idxv_rot (A,K)
    const int*   tir     = (const int*)  d_in[9];   // trace_idx_rot  (A,A)
    const int*   lvl     = (const int*)  d_in[10];  // lvl
    float* out = (float*)d_out;

    build_wt<<<512, 256>>>(W, kpw, idx_map, tivr, tir);
    mean_dir_k<<<BP_/256, 256>>>(nbr, verts);
    prep_small<<<1, 512>>>(kpw, vs, idx_map, tivr, bias, lvl);

    dim3 grid(BP_/64, DR_/96);
    equi_gemm<<<grid, 256>>>(fm, out);
}

// round 4
// speedup vs baseline: 3.8309x; 3.8309x over previous
#include <cuda_runtime.h>
#include <cstdint>
#include <cstddef>

#define B_   2
#define P_   8192
#define NNB  24
#define C1_  32
#define C2_  32
#define K_   13
#define A_   12
#define DR_  (C2_*A_)   /* 384 */
#define CA_  (C1_*A_)   /* 384 */
#define BP_  (B_*P_)    /* 16384 */

// ---- scratch (device globals; no allocation allowed) ----
__device__ float WTt_g[K_*DR_*CA_];  // [k][dr(384)][ca(384)], tf32-rounded (~7.7MB)
__device__ float md_g[BP_*3];        // mean_dir
__device__ float kpo_g[C2_*K_*3];    // normalized k_pos_ori [d][k][xyz]
__device__ float be_g[C2_*A_];       // bias_eff[d][r]

__device__ __forceinline__ uint32_t f2tf32(float x) {
    uint32_t u;
    asm("cvt.rna.tf32.f32 %0, %1;" : "=r"(u) : "f"(x));
    return u;
}

__device__ __forceinline__ void mma_tf32(float& c0, float& c1, float& c2, float& c3,
                                         uint32_t a0, uint32_t a1, uint32_t a2, uint32_t a3,
                                         uint32_t b0, uint32_t b1) {
    asm volatile("mma.sync.aligned.m16n8k8.row.col.f32.tf32.tf32.f32 "
                 "{%0,%1,%2,%3}, {%4,%5,%6,%7}, {%8,%9}, {%0,%1,%2,%3};"
                 : "+f"(c0), "+f"(c1), "+f"(c2), "+f"(c3)
                 : "r"(a0), "r"(a1), "r"(a2), "r"(a3), "r"(b0), "r"(b1));
}

// ===================== prep kernels =====================
__global__ void build_wt(const float* __restrict__ W,
                         const float* __restrict__ kpw,
                         const int*   __restrict__ idx_map,
                         const int*   __restrict__ tivr,
                         const int*   __restrict__ tir) {
    int idx = blockIdx.x * blockDim.x + threadIdx.x;
    const int total = K_*DR_*CA_;
    for (; idx < total; idx += gridDim.x * blockDim.x) {
        int ca = idx % CA_;
        int t  = idx / CA_;
        int n  = t % DR_;
        int k  = t / DR_;
        int d = n / A_, r = n % A_;
        int c = ca / A_, a = ca % A_;
        int j = idx_map[tivr[r*K_ + k]*A_ + tir[r*A_ + a]];
        float v = W[(d*C1_ + c)*36 + j] * kpw[d*36 + j];
        ((uint32_t*)WTt_g)[idx] = f2tf32(v);   // pre-round B to tf32
    }
}

__global__ void mean_dir_k(const int* __restrict__ nbr_idx,
                           const float* __restrict__ verts) {
    int bp = blockIdx.x * blockDim.x + threadIdx.x;
    if (bp >= BP_) return;
    int b = bp >> 13;
    int p = bp & (P_-1);
    const float* vb = verts + b * P_ * 3;
    float vx = vb[p*3+0], vy = vb[p*3+1], vz = vb[p*3+2];
    float sx = 0.f, sy = 0.f, sz = 0.f;
    const int* ni = nbr_idx + bp * NNB;
#pragma unroll 4
    for (int n = 0; n < NNB; n++) {
        int q = ni[n];
        float dx = vb[q*3+0] - vx;
        float dy = vb[q*3+1] - vy;
        float dz = vb[q*3+2] - vz;
        float nrm = sqrtf(dx*dx + dy*dy + dz*dz);
        float s = 1.0f / fmaxf(nrm, 1e-12f);
        sx += dx*s; sy += dy*s; sz += dz*s;
    }
    const float inv = 1.0f / (float)NNB;
    md_g[bp*3+0] = sx * inv;
    md_g[bp*3+1] = sy * inv;
    md_g[bp*3+2] = sz * inv;
}

__global__ void prep_small(const float* __restrict__ kpw,
                           const float* __restrict__ vs,
                           const int*   __restrict__ idx_map,
                           const int*   __restrict__ tivr,
                           const float* __restrict__ bias,
                           const int*   __restrict__ lvl) {
    int t = threadIdx.x;
    if (t < C2_*K_) {
        int d = t / K_, k = t % K_;
        float s0 = 0.f, s1 = 0.f, s2 = 0.f;
        for (int a = 0; a < A_; a++) {
            float w = kpw[d*36 + idx_map[k*A_ + a]];
            s0 += w * vs[a*3+0];
            s1 += w * vs[a*3+1];
            s2 += w * vs[a*3+2];
        }
        float nrm = sqrtf(s0*s0 + s1*s1 + s2*s2);
        float inv = 1.0f / fmaxf(nrm, 1e-12f);
        kpo_g[t*3+0] = s0*inv;
        kpo_g[t*3+1] = s1*inv;
        kpo_g[t*3+2] = s2*inv;
    }
    if (t < C2_*A_) {
        int d = t / A_, r = t % A_;
        float s = 0.f;
        for (int k = 0; k < K_; k++)
            s += bias[d*5 + lvl[tivr[r*K_ + k]]];
        be_g[t] = s;
    }
}

// ===================== main mma.sync tf32 kernel =====================
// smem (floats):
//   A_s [128][40]  @0        (5120)    K-permuted tf32 A chunk
//   B_s [192][40]  @5120     (7680)    K-permuted tf32 B chunk
//   ACC [128][200] @12800    (25600)   per-CTA output accumulator
//   PW  [128][17]  @38400    (2176)    pw[m][dl] for current k
//   MD  [128][3]   @40576
//   KPO [16][13][3]@40960
//   BE  [192]      @41584
#define OFF_A   0
#define OFF_B   5120
#define OFF_ACC 12800
#define OFF_PW  38400
#define OFF_MD  40576
#define OFF_KPO 40960
#define OFF_BE  41584
#define SMEM_FLOATS 41776
#define SMEM_BYTES (SMEM_FLOATS*4)

__global__ __launch_bounds__(256, 1) void equi_mma(const float* __restrict__ fm,
                                                   float* __restrict__ out) {
    extern __shared__ float s[];
    float* A_s = s + OFF_A;
    float* B_s = s + OFF_B;
    float* ACC = s + OFF_ACC;
    float* PW  = s + OFF_PW;
    float* MD  = s + OFF_MD;
    float* KPO = s + OFF_KPO;
    float* BE  = s + OFF_BE;

    const int tid  = threadIdx.x;
    const int wid  = tid >> 5;
    const int lane = tid & 31;
    const int gid  = lane >> 2;     // 0..7
    const int tig  = lane & 3;      // 0..3

    const int Ntile = blockIdx.x;        // 0..1
    const int Mtile = blockIdx.y;        // 0..127
    const int b  = Mtile >> 6;
    const int p0 = (Mtile & 63) << 7;
    const int n0 = Ntile * 192;
    const int d0 = Ntile * 16;

    const int wm = wid & 3;   // 0..3  -> m offset wm*32
    const int wn = wid >> 2;  // 0..1  -> n offset wn*96
    const int m0w = wm * 32;
    const int n0w = wn * 96;

    // stage small tables
    for (int i = tid; i < 128*3; i += 256) MD[i]  = md_g[(size_t)Mtile*128*3 + i];
    for (int i = tid; i < 16*K_*3; i += 256) KPO[i] = kpo_g[d0*(K_*3) + i];
    if (tid < 192) BE[tid] = be_g[d0*A_ + tid];

    // k-permuted store column for A: lane -> col
    const int colA = (lane & 24) + ((lane & 3) << 1) + ((lane >> 2) & 1);
    const int nB = tid >> 3;   // 0..31 (B row base)
    const int qB = tid & 7;    // float4 index within 32-float row

    const float* fmb = fm + (size_t)b * C1_ * K_ * P_ * A_;

    float acc[2][12][4];
#pragma unroll
    for (int mt = 0; mt < 2; mt++)
#pragma unroll
        for (int nt = 0; nt < 12; nt++)
#pragma unroll
            for (int q = 0; q < 4; q++) acc[mt][nt][q] = 0.f;

    float  av[16];
    float4 bv[6];

    auto prefetch = [&](int k, int j) {
        int ca = j*32 + lane;
        int c  = ca / 12;
        int a  = ca - c*12;
        const float* ap = fmb + ((size_t)(c*K_ + k)*P_ + p0 + wid*16)*A_ + a;
#pragma unroll
        for (int rr = 0; rr < 16; rr++) av[rr] = ap[rr*A_];
        const float* wp = WTt_g + (size_t)k*(DR_*CA_) + (size_t)(n0 + nB)*CA_ + j*32 + qB*4;
#pragma unroll
        for (int ss = 0; ss < 6; ss++) bv[ss] = *(const float4*)(wp + (size_t)ss*32*CA_);
    };

    prefetch(0, 0);

    int k = 0, j = 0;
    for (int t = 0; t < K_*12; t++) {
        __syncthreads();   // previous chunk's mma reads + previous fold's PW reads done

        // ---- STS A (tf32 round), k-permuted cols ----
#pragma unroll
        for (int rr = 0; rr < 16; rr++)
            ((uint32_t*)A_s)[(wid*16 + rr)*40 + colA] = f2tf32(av[rr]);
        // ---- STS B (already tf32), k-permuted cols ----
#pragma unroll
        for (int ss = 0; ss < 6; ss++) {
            float vv[4] = {bv[ss].x, bv[ss].y, bv[ss].z, bv[ss].w};
#pragma unroll
            for (int i = 0; i < 4; i++) {
                int col = (qB >> 1)*8 + (i << 1) + (qB & 1);
                B_s[(nB + 32*ss)*40 + col] = vv[i];
            }
        }
        __syncthreads();   // smem chunk ready

        // per-k pw table (written once per segment; read at fold 11 chunks later)
        if (j == 0) {
#pragma unroll
            for (int i = 0; i < 8; i++) {
                int e  = i*256 + tid;
                int m  = e & 127;
                int dl = e >> 7;
                const float* kp = KPO + (dl*K_ + k)*3;
                float w = MD[m*3+0]*kp[0] + MD[m*3+1]*kp[1] + MD[m*3+2]*kp[2];
                PW[m*17 + dl] = fmaxf(w, 0.f);
            }
        }

        // prefetch next chunk (overlaps mma)
        int j2 = j + 1, k2 = k;
        if (j2 == 12) { j2 = 0; k2++; }
        if (k2 < K_) prefetch(k2, j2);

        // ---- mma over 4 k8-steps ----
#pragma unroll
        for (int ks = 0; ks < 4; ks++) {
            uint32_t bb[12][2];
#pragma unroll
            for (int nt = 0; nt < 12; nt++) {
                float2 v = *(const float2*)&B_s[(n0w + nt*8 + gid)*40 + ks*8 + tig*2];
                bb[nt][0] = __float_as_uint(v.x);
                bb[nt][1] = __float_as_uint(v.y);
            }
#pragma unroll
            for (int mt = 0; mt < 2; mt++) {
                int rb = m0w + mt*16 + gid;
                float2 alo = *(const float2*)&A_s[rb*40 + ks*8 + tig*2];       // a0,a2
                float2 ahi = *(const float2*)&A_s[(rb+8)*40 + ks*8 + tig*2];   // a1,a3
                uint32_t a0 = __float_as_uint(alo.x);
                uint32_t a1 = __float_as_uint(ahi.x);
                uint32_t a2 = __float_as_uint(alo.y);
                uint32_t a3 = __float_as_uint(ahi.y);
#pragma unroll
                for (int nt = 0; nt < 12; nt++)
                    mma_tf32(acc[mt][nt][0], acc[mt][nt][1], acc[mt][nt][2], acc[mt][nt][3],
                             a0, a1, a2, a3, bb[nt][0], bb[nt][1]);
            }
        }

        // ---- end of k-segment: fold pw into ACC (thread-private cells, no sync) ----
        if (j == 11) {
#pragma unroll
            for (int mt = 0; mt < 2; mt++) {
                int r0 = m0w + mt*16 + gid;
                int r1 = r0 + 8;
#pragma unroll
                for (int nt = 0; nt < 12; nt++) {
                    int n  = n0w + nt*8 + tig*2;
                    int dl = n / 12;
                    float pw0 = PW[r0*17 + dl];
                    float pw1 = PW[r1*17 + dl];
                    float2* c0p = (float2*)&ACC[r0*200 + n];
                    float2* c1p = (float2*)&ACC[r1*200 + n];
                    if (k == 0) {
                        *c0p = make_float2(pw0*acc[mt][nt][0], pw0*acc[mt][nt][1]);
                        *c1p = make_float2(pw1*acc[mt][nt][2], pw1*acc[mt][nt][3]);
                    } else {
                        float2 c0 = *c0p, c1 = *c1p;
                        c0.x = fmaf(pw0, acc[mt][nt][0], c0.x);
                        c0.y = fmaf(pw0, acc[mt][nt][1], c0.y);
                        c1.x = fmaf(pw1, acc[mt][nt][2], c1.x);
                        c1.y = fmaf(pw1, acc[mt][nt][3], c1.y);
                        *c0p = c0; *c1p = c1;
                    }
                    acc[mt][nt][0] = 0.f; acc[mt][nt][1] = 0.f;
                    acc[mt][nt][2] = 0.f; acc[mt][nt][3] = 0.f;
                }
            }
        }
        j = j2; k = k2;
    }

    __syncthreads();

    // ---- final: bias + relu, store out[b, d, p, r] ----
    {
        int m = tid & 127;
        int h = tid >> 7;
#pragma unroll
        for (int i = 0; i < 8; i++) {
            int dl = i*2 + h;
            float4 x0 = *(const float4*)&ACC[m*200 + dl*12 + 0];
            float4 x1 = *(const float4*)&ACC[m*200 + dl*12 + 4];
            float4 x2 = *(const float4*)&ACC[m*200 + dl*12 + 8];
            const float* bb = BE + dl*12;
            float4 y0 = make_float4(fmaxf(x0.x + bb[0], 0.f), fmaxf(x0.y + bb[1], 0.f),
                                    fmaxf(x0.z + bb[2], 0.f), fmaxf(x0.w + bb[3], 0.f));
            float4 y1 = make_float4(fmaxf(x1.x + bb[4], 0.f), fmaxf(x1.y + bb[5], 0.f),
                                    fmaxf(x1.z + bb[6], 0.f), fmaxf(x1.w + bb[7], 0.f));
            float4 y2 = make_float4(fmaxf(x2.x + bb[8], 0.f), fmaxf(x2.y + bb[9], 0.f),
                                    fmaxf(x2.z + bb[10], 0.f), fmaxf(x2.w + bb[11], 0.f));
            float* op = out + ((size_t)(b*C2_ + d0 + dl)*P_ + p0 + m)*A_;
            *(float4*)(op + 0) = y0;
            *(float4*)(op + 4) = y1;
            *(float4*)(op + 8) = y2;
        }
    }
}

// ---------------------------------------------------------------------------
extern "C" void kernel_launch(void* const* d_in, const int* in_sizes, int n_in,
                              void* d_out, int out_size) {
    const int*   nbr     = (const int*)  d_in[0];
    const float* verts   = (const float*)d_in[1];
    const float* fm      = (const float*)d_in[2];
    const float* W       = (const float*)d_in[3];
    const float* bias    = (const float*)d_in[4];
    const float* kpw     = (const float*)d_in[5];
    const float* vs      = (const float*)d_in[6];
    const int*   idx_map = (const int*)  d_in[7];
    const int*   tivr    = (const int*)  d_in[8];
    const int*   tir     = (const int*)  d_in[9];
    const int*   lvl     = (const int*)  d_in[10];
    float* out = (float*)d_out;

    static int smem_set = 0;
    if (!smem_set) {
        cudaFuncSetAttribute(equi_mma, cudaFuncAttributeMaxDynamicSharedMemorySize, SMEM_BYTES);
        smem_set = 1;
    }

    build_wt<<<512, 256>>>(W, kpw, idx_map, tivr, tir);
    mean_dir_k<<<BP_/256, 256>>>(nbr, verts);
    prep_small<<<1, 512>>>(kpw, vs, idx_map, tivr, bias, lvl);

    dim3 grid(2, 128);
    equi_mma<<<grid, 256, SMEM_BYTES>>>(fm, out);
}